// round 7
// baseline (speedup 1.0000x reference)
#include <cuda_runtime.h>

// Problem constants (fixed by the dataset)
#define N_BATCH 2
#define HW 65536          // 256*256
#define NRAYS 32768       // N_BATCH * 16384
#define RPB 4             // rays (warps) per block
#define THREADS 128

typedef unsigned long long u64;

// channels-last copy of the planes: [(n*3+p)][hw][c]
__device__ float g_planesT[(size_t)N_BATCH * 3 * HW * 32];

// ---- weight pack: filled by prep kernel, copied to __constant__ ----
struct WPack {
    ulonglong2 w1[512];    // [c][16 x u64x2]  : layer1 weights, [c][j] f32 pairs
    ulonglong2 w2r[512];   // [j][8 x u64x2]   : layer2 rgb columns
    u64   b1[32];          // layer1 bias as f32 pairs
    u64   b2r[16];         // layer2 rgb bias as f32 pairs
    float w2sig[64];       // layer2 sigma column
    float b2sig;
    float pad[3];
};
__device__ WPack g_wp;
__constant__ WPack c_wp;

// ---------- packed f32x2 helpers ----------
__device__ __forceinline__ u64 ffma2(u64 a, u64 b, u64 c) {
    u64 r; asm("fma.rn.f32x2 %0,%1,%2,%3;" : "=l"(r) : "l"(a), "l"(b), "l"(c)); return r;
}
__device__ __forceinline__ u64 pack2(float lo, float hi) {
    u64 r; asm("mov.b64 %0,{%1,%2};" : "=l"(r) : "f"(lo), "f"(hi)); return r;
}
__device__ __forceinline__ void unpack2(u64 d, float& lo, float& hi) {
    asm("mov.b64 {%0,%1},%2;" : "=f"(lo), "=f"(hi) : "l"(d));
}
__device__ __forceinline__ float softplus_f(float x) {
    return fmaxf(x, 0.f) + __logf(1.f + __expf(-fabsf(x)));
}

// ---------- kernel 0: [np][C][HW] -> [np][HW][C] tiled transpose ----------
__global__ void transpose_kernel(const float* __restrict__ in) {
    __shared__ float tile[32][33];
    int np  = blockIdx.y;
    int hw0 = blockIdx.x * 32;
    int tx = threadIdx.x, ty = threadIdx.y;
#pragma unroll
    for (int i = 0; i < 4; i++) {
        int cc = ty * 4 + i;
        tile[cc][tx] = in[(np * 32 + cc) * HW + hw0 + tx];
    }
    __syncthreads();
#pragma unroll
    for (int i = 0; i < 4; i++) {
        int row = ty * 4 + i;
        g_planesT[(size_t)(np * HW + hw0 + row) * 32 + tx] = tile[tx][row];
    }
}

// ---------- kernel 0b: build the weight pack ----------
__global__ void prep_pack_kernel(const float* __restrict__ w1,
                                 const float* __restrict__ b1,
                                 const float* __restrict__ w2,
                                 const float* __restrict__ b2) {
    int t = threadIdx.x;
    float* fw1  = (float*)g_wp.w1;
    float* fw2r = (float*)g_wp.w2r;
    float* fb1  = (float*)g_wp.b1;
    float* fb2r = (float*)g_wp.b2r;
    for (int i = t; i < 2048; i += 256) fw1[i] = w1[i];          // [c][j]
    for (int i = t; i < 64 * 33; i += 256) {
        int j = i / 33, k = i - j * 33;
        float v = w2[i];
        if (k == 0) g_wp.w2sig[j] = v; else fw2r[j * 32 + (k - 1)] = v;
    }
    if (t < 64) fb1[t] = b1[t];
    if (t < 32) fb2r[t] = b2[t + 1];
    if (t == 0) { g_wp.b2sig = b2[0]; g_wp.pad[0] = 0.f; g_wp.pad[1] = 0.f; g_wp.pad[2] = 0.f; }
}

// ---------- kernel 1: full renderer, one warp per ray ----------
__global__ __launch_bounds__(THREADS, 4) void render_kernel(
    const float* __restrict__ orig, const float* __restrict__ dirs,
    float* __restrict__ out)
{
    __shared__ int2  taps[RPB][32][12];            // (addr, weight-bits)
    __shared__ float feats[RPB][32 * 33];          // [s][c], pad 33

    const int tid = threadIdx.x;
    const int w = tid >> 5, lane = tid & 31;
    const int rg = blockIdx.x * RPB + w;   // global ray id
    const int n  = rg >> 14;               // batch index

    const float ox = orig[rg * 3 + 0], oy = orig[rg * 3 + 1], oz = orig[rg * 3 + 2];
    const float dx = dirs[rg * 3 + 0], dy = dirs[rg * 3 + 1], dz = dirs[rg * 3 + 2];

    // ---- stage 1: thread = sample. Compute 12 (addr, weight) taps ----
    const float t   = (lane + 0.5f) * 0.03125f;
    const float dep = 2.25f + 1.05f * t;
    const float cx = 2.f * fmaf(dep, dx, ox);
    const float cy = 2.f * fmaf(dep, dy, oy);
    const float cz = 2.f * fmaf(dep, dz, oz);

#pragma unroll
    for (int p = 0; p < 3; p++) {
        float u = (p == 0) ? cx : (p == 1) ? cy : cx;
        float v = (p == 0) ? cy : (p == 1) ? cz : cz;
        float ix = ((u + 1.f) * 0.5f) * 255.f;
        float iy = ((v + 1.f) * 0.5f) * 255.f;
        float fx0 = floorf(ix), fy0 = floorf(iy);
        float a0 = ix - fx0, a1 = (fx0 + 1.f) - ix;   // match ref's unclamped weights
        float bb0 = iy - fy0, bb1 = (fy0 + 1.f) - iy;
        int ix0 = (int)fminf(fmaxf(fx0, 0.f), 255.f);
        int ix1 = (int)fminf(fmaxf(fx0 + 1.f, 0.f), 255.f);
        int iy0 = (int)fminf(fmaxf(fy0, 0.f), 255.f);
        int iy1 = (int)fminf(fmaxf(fy0 + 1.f, 0.f), 255.f);
        int base = (n * 3 + p) * (HW * 32);
        int r0 = base + iy0 * (256 * 32);
        int r1 = base + iy1 * (256 * 32);
        taps[w][lane][p * 4 + 0] = make_int2(r0 + ix0 * 32, __float_as_int(a1 * bb1));
        taps[w][lane][p * 4 + 1] = make_int2(r0 + ix1 * 32, __float_as_int(a0 * bb1));
        taps[w][lane][p * 4 + 2] = make_int2(r1 + ix0 * 32, __float_as_int(a1 * bb0));
        taps[w][lane][p * 4 + 3] = make_int2(r1 + ix1 * 32, __float_as_int(a0 * bb0));
    }
    __syncwarp();

    // ---- stage 2: vectorized gather. 4 tap-groups x 8 channel-lanes. ----
    {
        const int g    = lane >> 3;          // tap group 0..3
        const int cpos = (lane & 7) * 4;     // channel base within float4
        const int cstore = cpos + g;         // channel this lane stores after reduce
        const unsigned FULL = 0xffffffffu;
#pragma unroll 4
        for (int s = 0; s < 32; s++) {
            float a0 = 0.f, a1 = 0.f, a2 = 0.f, a3 = 0.f;
#pragma unroll
            for (int r = 0; r < 3; r++) {
                int2 tw = taps[w][s][r * 4 + g];
                float wt = __int_as_float(tw.y);
                const float4 v = *(const float4*)&g_planesT[tw.x + cpos];
                a0 = fmaf(wt, v.x, a0);
                a1 = fmaf(wt, v.y, a1);
                a2 = fmaf(wt, v.z, a2);
                a3 = fmaf(wt, v.w, a3);
            }
#pragma unroll
            for (int off = 8; off <= 16; off <<= 1) {
                a0 += __shfl_xor_sync(FULL, a0, off);
                a1 += __shfl_xor_sync(FULL, a1, off);
                a2 += __shfl_xor_sync(FULL, a2, off);
                a3 += __shfl_xor_sync(FULL, a3, off);
            }
            float val = (g == 0) ? a0 : (g == 1) ? a1 : (g == 2) ? a2 : a3;
            feats[w][s * 33 + cstore] = val * (1.f / 3.f);
        }
    }
    __syncwarp();

    // ---- phase B: thread = sample. MLP, weights from the constant port. ----
    const float* frow = &feats[w][lane * 33];

    float sig = c_wp.b2sig;
    u64 acc2[16];
#pragma unroll
    for (int k = 0; k < 16; k++) acc2[k] = c_wp.b2r[k];

#pragma unroll
    for (int half = 0; half < 2; half++) {
        u64 acc[16];
#pragma unroll
        for (int jp = 0; jp < 16; jp++) acc[jp] = c_wp.b1[half * 16 + jp];

#pragma unroll 4
        for (int cc = 0; cc < 32; cc++) {
            float fc = frow[cc];
            u64 fc2 = pack2(fc, fc);
#pragma unroll
            for (int jq = 0; jq < 8; jq++) {
                ulonglong2 ww = c_wp.w1[cc * 16 + half * 8 + jq];
                acc[2 * jq]     = ffma2(fc2, ww.x, acc[2 * jq]);
                acc[2 * jq + 1] = ffma2(fc2, ww.y, acc[2 * jq + 1]);
            }
        }
        // consume these 32 hidden units into layer 2 immediately
#pragma unroll 4
        for (int jp = 0; jp < 16; jp++) {
            float lo, hi; unpack2(acc[jp], lo, hi);
            int j0 = half * 32 + 2 * jp;
            float h0 = softplus_f(lo);
            float h1 = softplus_f(hi);
            sig = fmaf(h0, c_wp.w2sig[j0], sig);
            sig = fmaf(h1, c_wp.w2sig[j0 + 1], sig);
            u64 h02 = pack2(h0, h0);
            u64 h12 = pack2(h1, h1);
#pragma unroll
            for (int kq = 0; kq < 8; kq++) {
                ulonglong2 ww0 = c_wp.w2r[j0 * 8 + kq];
                ulonglong2 ww1 = c_wp.w2r[(j0 + 1) * 8 + kq];
                u64 v0 = ffma2(h02, ww0.x, acc2[2 * kq]);
                u64 v1 = ffma2(h02, ww0.y, acc2[2 * kq + 1]);
                acc2[2 * kq]     = ffma2(h12, ww1.x, v0);
                acc2[2 * kq + 1] = ffma2(h12, ww1.y, v1);
            }
        }
    }

    float rgb[32];
#pragma unroll
    for (int k = 0; k < 16; k++) {
        float lo, hi; unpack2(acc2[k], lo, hi);
        rgb[2 * k]     = __fdividef(1.002f, 1.f + __expf(-lo)) - 0.001f;
        rgb[2 * k + 1] = __fdividef(1.002f, 1.f + __expf(-hi)) - 0.001f;
    }

    // ---- ray marching: warp scan over samples (lane = s) ----
    const unsigned FULL = 0xffffffffu;
    float sig_n = __shfl_down_sync(FULL, sig, 1);
    float dep_n = __shfl_down_sync(FULL, dep, 1);
    float alpha;
    if (lane < 31) {
        float delta = dep_n - dep;
        float dm = 0.5f * (sig + sig_n);
        float dens = softplus_f(dm - 1.f);
        alpha = 1.f - __expf(-delta * dens);
    } else {
        alpha = 0.f;
    }
    float gg = 1.f - alpha + 1e-10f;
    float pscan = gg;
#pragma unroll
    for (int off = 1; off < 32; off <<= 1) {
        float v = __shfl_up_sync(FULL, pscan, off);
        if (lane >= off) pscan *= v;
    }
    float T = __shfl_up_sync(FULL, pscan, 1);
    if (lane == 0) T = 1.f;
    float wgt = alpha * T;                      // weights[s], s<31 (lane31 -> 0)
    float wprev = __shfl_up_sync(FULL, wgt, 1);
    if (lane == 0) wprev = 0.f;
    float coeff = 0.5f * (wgt + wprev);         // contribution of rgb[s] to the sum

#pragma unroll
    for (int k = 0; k < 32; k++) rgb[k] *= coeff;
#pragma unroll
    for (int off = 16; off >= 1; off >>= 1) {
#pragma unroll
        for (int k = 0; k < 32; k++) rgb[k] += __shfl_xor_sync(FULL, rgb[k], off);
    }
    if (lane == 0) {
        float4* o4 = (float4*)(out + rg * 32);
#pragma unroll
        for (int k = 0; k < 8; k++)
            o4[k] = make_float4(rgb[4 * k], rgb[4 * k + 1], rgb[4 * k + 2], rgb[4 * k + 3]);
    }
}

extern "C" void kernel_launch(void* const* d_in, const int* in_sizes, int n_in,
                              void* d_out, int out_size) {
    const float* vol  = (const float*)d_in[0];  // [2,3,32,256,256]
    const float* orig = (const float*)d_in[1];  // [2,16384,3]
    const float* dirs = (const float*)d_in[2];  // [2,16384,3]
    const float* w1   = (const float*)d_in[3];  // [32,64]
    const float* b1   = (const float*)d_in[4];  // [64]
    const float* w2   = (const float*)d_in[5];  // [64,33]
    const float* b2   = (const float*)d_in[6];  // [33]
    float* out = (float*)d_out;

    dim3 tb(32, 8);
    dim3 tg(HW / 32, N_BATCH * 3);
    transpose_kernel<<<tg, tb>>>(vol);

    prep_pack_kernel<<<1, 256>>>(w1, b1, w2, b2);

    void* gaddr = nullptr;
    cudaGetSymbolAddress(&gaddr, g_wp);
    cudaMemcpyToSymbolAsync(c_wp, gaddr, sizeof(WPack), 0,
                            cudaMemcpyDeviceToDevice, 0);

    render_kernel<<<NRAYS / RPB, THREADS>>>(orig, dirs, out);
}

// round 8
// speedup vs baseline: 1.3293x; 1.3293x over previous
#include <cuda_runtime.h>

// Problem constants (fixed by the dataset)
#define N_BATCH 2
#define HW 65536          // 256*256
#define NRAYS 32768       // N_BATCH * 16384
#define RPW 2             // rays per warp
#define RPB 8             // rays per block (4 warps x 2)
#define THREADS 128

typedef unsigned long long u64;

// channels-last copy of the planes: [(n*3+p)][hw][c]
__device__ float g_planesT[(size_t)N_BATCH * 3 * HW * 32];

// ---- dynamic smem layout (bytes) ----
#define SM_W1S    0        // 2048 f32  [c][j]
#define SM_W2RS   8192     // 2048 f32  [j][32 rgb outputs]
#define SM_B1S    16384    // 64 f32
#define SM_W2SIG  16640    // 64 f32
#define SM_B2RS   16896    // 32 f32
#define SM_B2SIG  17024    // 1 f32
#define SM_TAPS   17152    // 4 warps x 32 x 12 int2 = 12288
#define SM_FEATS  29440    // 4 warps x 2 rays x (32*33) f32 = 33792
#define SM_TOTAL  63360

// ---------- packed f32x2 helpers ----------
__device__ __forceinline__ u64 ffma2(u64 a, u64 b, u64 c) {
    u64 r; asm("fma.rn.f32x2 %0,%1,%2,%3;" : "=l"(r) : "l"(a), "l"(b), "l"(c)); return r;
}
__device__ __forceinline__ u64 pack2(float lo, float hi) {
    u64 r; asm("mov.b64 %0,{%1,%2};" : "=l"(r) : "f"(lo), "f"(hi)); return r;
}
__device__ __forceinline__ void unpack2(u64 d, float& lo, float& hi) {
    asm("mov.b64 {%0,%1},%2;" : "=f"(lo), "=f"(hi) : "l"(d));
}
__device__ __forceinline__ float softplus_f(float x) {
    return fmaxf(x, 0.f) + __logf(1.f + __expf(-fabsf(x)));
}

// ---------- kernel 0: [np][C][HW] -> [np][HW][C] tiled transpose ----------
__global__ void transpose_kernel(const float* __restrict__ in) {
    __shared__ float tile[32][33];
    int np  = blockIdx.y;
    int hw0 = blockIdx.x * 32;
    int tx = threadIdx.x, ty = threadIdx.y;
#pragma unroll
    for (int i = 0; i < 4; i++) {
        int cc = ty * 4 + i;
        tile[cc][tx] = in[(np * 32 + cc) * HW + hw0 + tx];
    }
    __syncthreads();
#pragma unroll
    for (int i = 0; i < 4; i++) {
        int row = ty * 4 + i;
        g_planesT[(size_t)(np * HW + hw0 + row) * 32 + tx] = tile[tx][row];
    }
}

// ---------- kernel 1: renderer, one warp per 2 rays ----------
__global__ __launch_bounds__(THREADS, 3) void render_kernel(
    const float* __restrict__ orig, const float* __restrict__ dirs,
    const float* __restrict__ w1, const float* __restrict__ b1,
    const float* __restrict__ w2, const float* __restrict__ b2,
    float* __restrict__ out)
{
    extern __shared__ __align__(16) unsigned char smem[];
    float* w1s    = (float*)(smem + SM_W1S);
    float* w2rs   = (float*)(smem + SM_W2RS);
    float* b1s    = (float*)(smem + SM_B1S);
    float* w2sigs = (float*)(smem + SM_W2SIG);
    float* b2rs   = (float*)(smem + SM_B2RS);
    float* b2sigp = (float*)(smem + SM_B2SIG);
    int2*  taps   = (int2*)(smem + SM_TAPS);
    float* featsb = (float*)(smem + SM_FEATS);

    const int tid = threadIdx.x;
    for (int i = tid; i < 2048; i += THREADS) w1s[i] = w1[i];
    if (tid < 64) b1s[tid] = b1[tid];
    for (int i = tid; i < 64 * 33; i += THREADS) {
        int j = i / 33, k = i - j * 33;
        float v = w2[i];
        if (k == 0) w2sigs[j] = v; else w2rs[j * 32 + (k - 1)] = v;
    }
    if (tid < 32) b2rs[tid] = b2[tid + 1];
    if (tid == 0) b2sigp[0] = b2[0];
    __syncthreads();

    const int w = tid >> 5, lane = tid & 31;
    const int rg0 = blockIdx.x * RPB + w * RPW;   // first ray of this warp
    const unsigned FULL = 0xffffffffu;

    const float t   = (lane + 0.5f) * 0.03125f;
    const float dep = 2.25f + 1.05f * t;

    // ---- stage 1+2 per ray: taps then gather into feats[w][r] ----
#pragma unroll
    for (int r = 0; r < RPW; r++) {
        const int rg = rg0 + r;
        const int n  = rg >> 14;
        const float ox = orig[rg * 3 + 0], oy = orig[rg * 3 + 1], oz = orig[rg * 3 + 2];
        const float dx = dirs[rg * 3 + 0], dy = dirs[rg * 3 + 1], dz = dirs[rg * 3 + 2];
        const float cx = 2.f * fmaf(dep, dx, ox);
        const float cy = 2.f * fmaf(dep, dy, oy);
        const float cz = 2.f * fmaf(dep, dz, oz);

#pragma unroll
        for (int p = 0; p < 3; p++) {
            float u = (p == 0) ? cx : (p == 1) ? cy : cx;
            float v = (p == 0) ? cy : (p == 1) ? cz : cz;
            float ix = ((u + 1.f) * 0.5f) * 255.f;
            float iy = ((v + 1.f) * 0.5f) * 255.f;
            float fx0 = floorf(ix), fy0 = floorf(iy);
            float a0 = ix - fx0, a1 = (fx0 + 1.f) - ix;
            float bb0 = iy - fy0, bb1 = (fy0 + 1.f) - iy;
            int ix0 = (int)fminf(fmaxf(fx0, 0.f), 255.f);
            int ix1 = (int)fminf(fmaxf(fx0 + 1.f, 0.f), 255.f);
            int iy0 = (int)fminf(fmaxf(fy0, 0.f), 255.f);
            int iy1 = (int)fminf(fmaxf(fy0 + 1.f, 0.f), 255.f);
            int base = (n * 3 + p) * (HW * 32);
            int r0 = base + iy0 * (256 * 32);
            int r1 = base + iy1 * (256 * 32);
            int o = (w * 32 + lane) * 12 + p * 4;
            taps[o + 0] = make_int2(r0 + ix0 * 32, __float_as_int(a1 * bb1));
            taps[o + 1] = make_int2(r0 + ix1 * 32, __float_as_int(a0 * bb1));
            taps[o + 2] = make_int2(r1 + ix0 * 32, __float_as_int(a1 * bb0));
            taps[o + 3] = make_int2(r1 + ix1 * 32, __float_as_int(a0 * bb0));
        }
        __syncwarp();

        {
            const int g    = lane >> 3;
            const int cpos = (lane & 7) * 4;
            const int cstore = cpos + g;
            float* feats = featsb + (w * 2 + r) * (32 * 33);
#pragma unroll 4
            for (int s = 0; s < 32; s++) {
                float a0 = 0.f, a1 = 0.f, a2 = 0.f, a3 = 0.f;
#pragma unroll
                for (int q = 0; q < 3; q++) {
                    int2 tw = taps[(w * 32 + s) * 12 + q * 4 + g];
                    float wt = __int_as_float(tw.y);
                    const float4 v = *(const float4*)&g_planesT[tw.x + cpos];
                    a0 = fmaf(wt, v.x, a0);
                    a1 = fmaf(wt, v.y, a1);
                    a2 = fmaf(wt, v.z, a2);
                    a3 = fmaf(wt, v.w, a3);
                }
#pragma unroll
                for (int off = 8; off <= 16; off <<= 1) {
                    a0 += __shfl_xor_sync(FULL, a0, off);
                    a1 += __shfl_xor_sync(FULL, a1, off);
                    a2 += __shfl_xor_sync(FULL, a2, off);
                    a3 += __shfl_xor_sync(FULL, a3, off);
                }
                float val = (g == 0) ? a0 : (g == 1) ? a1 : (g == 2) ? a2 : a3;
                feats[s * 33 + cstore] = val * (1.f / 3.f);
            }
        }
        __syncwarp();
    }

    // ---- MLP for both samples (lane's sample of ray0 and ray1) ----
    const float* frow0 = featsb + (w * 2 + 0) * (32 * 33) + lane * 33;
    const float* frow1 = featsb + (w * 2 + 1) * (32 * 33) + lane * 33;

    const float b2sig = b2sigp[0];
    float sig0 = b2sig, sig1 = b2sig;
    u64 a20[16], a21[16];
    const u64* b2d = (const u64*)b2rs;
#pragma unroll
    for (int k = 0; k < 16; k++) { a20[k] = b2d[k]; a21[k] = b2d[k]; }

    const ulonglong2* w1d2 = (const ulonglong2*)w1s;
    const ulonglong2* w2d2 = (const ulonglong2*)w2rs;
    const u64* b1d = (const u64*)b1s;

#pragma unroll
    for (int q = 0; q < 4; q++) {       // 16 hidden units per quarter
        u64 ac0[8], ac1[8];
#pragma unroll
        for (int jp = 0; jp < 8; jp++) { ac0[jp] = b1d[q * 8 + jp]; ac1[jp] = ac0[jp]; }

#pragma unroll 4
        for (int cc = 0; cc < 32; cc++) {
            float f0 = frow0[cc], f1 = frow1[cc];
            u64 f02 = pack2(f0, f0), f12 = pack2(f1, f1);
            const ulonglong2* wr = w1d2 + cc * 16 + q * 4;
#pragma unroll
            for (int jq = 0; jq < 4; jq++) {
                ulonglong2 ww = wr[jq];
                ac0[2 * jq]     = ffma2(f02, ww.x, ac0[2 * jq]);
                ac0[2 * jq + 1] = ffma2(f02, ww.y, ac0[2 * jq + 1]);
                ac1[2 * jq]     = ffma2(f12, ww.x, ac1[2 * jq]);
                ac1[2 * jq + 1] = ffma2(f12, ww.y, ac1[2 * jq + 1]);
            }
        }
        // consume the 16 hidden units of this quarter into layer 2
#pragma unroll 4
        for (int jp = 0; jp < 8; jp++) {
            int j0 = q * 16 + 2 * jp;
            float l0, h0, l1, h1;
            unpack2(ac0[jp], l0, h0);
            unpack2(ac1[jp], l1, h1);
            float h00 = softplus_f(l0), h01 = softplus_f(h0);
            float h10 = softplus_f(l1), h11 = softplus_f(h1);
            float ws0 = w2sigs[j0], ws1 = w2sigs[j0 + 1];
            sig0 = fmaf(h00, ws0, sig0); sig0 = fmaf(h01, ws1, sig0);
            sig1 = fmaf(h10, ws0, sig1); sig1 = fmaf(h11, ws1, sig1);
            u64 p00 = pack2(h00, h00), p01 = pack2(h01, h01);
            u64 p10 = pack2(h10, h10), p11 = pack2(h11, h11);
            const ulonglong2* wr0 = w2d2 + j0 * 8;
#pragma unroll
            for (int kq = 0; kq < 8; kq++) {
                ulonglong2 ww0 = wr0[kq];
                ulonglong2 ww1 = wr0[8 + kq];
                u64 v0 = ffma2(p00, ww0.x, a20[2 * kq]);
                u64 v1 = ffma2(p00, ww0.y, a20[2 * kq + 1]);
                a20[2 * kq]     = ffma2(p01, ww1.x, v0);
                a20[2 * kq + 1] = ffma2(p01, ww1.y, v1);
                u64 u0 = ffma2(p10, ww0.x, a21[2 * kq]);
                u64 u1 = ffma2(p10, ww0.y, a21[2 * kq + 1]);
                a21[2 * kq]     = ffma2(p11, ww1.x, u0);
                a21[2 * kq + 1] = ffma2(p11, ww1.y, u1);
            }
        }
    }

    // ---- ray marching per ray: warp scan over samples (lane = s) ----
#pragma unroll
    for (int r = 0; r < RPW; r++) {
        float sig = (r == 0) ? sig0 : sig1;
        float rgb[32];
#pragma unroll
        for (int k = 0; k < 16; k++) {
            u64 av = (r == 0) ? a20[k] : a21[k];
            float lo, hi; unpack2(av, lo, hi);
            rgb[2 * k]     = __fdividef(1.002f, 1.f + __expf(-lo)) - 0.001f;
            rgb[2 * k + 1] = __fdividef(1.002f, 1.f + __expf(-hi)) - 0.001f;
        }

        float sig_n = __shfl_down_sync(FULL, sig, 1);
        float dep_n = __shfl_down_sync(FULL, dep, 1);
        float alpha;
        if (lane < 31) {
            float delta = dep_n - dep;
            float dm = 0.5f * (sig + sig_n);
            float dens = softplus_f(dm - 1.f);
            alpha = 1.f - __expf(-delta * dens);
        } else {
            alpha = 0.f;
        }
        float gg = 1.f - alpha + 1e-10f;
        float pscan = gg;
#pragma unroll
        for (int off = 1; off < 32; off <<= 1) {
            float v = __shfl_up_sync(FULL, pscan, off);
            if (lane >= off) pscan *= v;
        }
        float T = __shfl_up_sync(FULL, pscan, 1);
        if (lane == 0) T = 1.f;
        float wgt = alpha * T;
        float wprev = __shfl_up_sync(FULL, wgt, 1);
        if (lane == 0) wprev = 0.f;
        float coeff = 0.5f * (wgt + wprev);

#pragma unroll
        for (int k = 0; k < 32; k++) rgb[k] *= coeff;
#pragma unroll
        for (int off = 16; off >= 1; off >>= 1) {
#pragma unroll
            for (int k = 0; k < 32; k++) rgb[k] += __shfl_xor_sync(FULL, rgb[k], off);
        }
        if (lane == 0) {
            float4* o4 = (float4*)(out + (rg0 + r) * 32);
#pragma unroll
            for (int k = 0; k < 8; k++)
                o4[k] = make_float4(rgb[4 * k], rgb[4 * k + 1], rgb[4 * k + 2], rgb[4 * k + 3]);
        }
    }
}

extern "C" void kernel_launch(void* const* d_in, const int* in_sizes, int n_in,
                              void* d_out, int out_size) {
    const float* vol  = (const float*)d_in[0];  // [2,3,32,256,256]
    const float* orig = (const float*)d_in[1];  // [2,16384,3]
    const float* dirs = (const float*)d_in[2];  // [2,16384,3]
    const float* w1   = (const float*)d_in[3];  // [32,64]
    const float* b1   = (const float*)d_in[4];  // [64]
    const float* w2   = (const float*)d_in[5];  // [64,33]
    const float* b2   = (const float*)d_in[6];  // [33]
    float* out = (float*)d_out;

    static int inited = 0;
    if (!inited) {
        cudaFuncSetAttribute(render_kernel,
                             cudaFuncAttributeMaxDynamicSharedMemorySize, SM_TOTAL);
        inited = 1;
    }

    dim3 tb(32, 8);
    dim3 tg(HW / 32, N_BATCH * 3);
    transpose_kernel<<<tg, tb>>>(vol);

    render_kernel<<<NRAYS / RPB, THREADS, SM_TOTAL>>>(orig, dirs, w1, b1, w2, b2, out);
}

// round 9
// speedup vs baseline: 1.9130x; 1.4391x over previous
#include <cuda_runtime.h>

// Problem constants (fixed by the dataset)
#define N_BATCH 2
#define HW 65536          // 256*256
#define NRAYS 32768       // N_BATCH * 16384
#define RPW 2             // rays per warp
#define RPB 8             // rays per block (4 warps x 2)
#define THREADS 128

typedef unsigned long long u64;

// channels-last copy of the planes: [(n*3+p)][hw][c]
__device__ float g_planesT[(size_t)N_BATCH * 3 * HW * 32];

// ---- dynamic smem layout (bytes) ----
#define SM_W1S    0        // 2048 f32  [c][j]
#define SM_W2RS   8192     // 2048 f32  [j][32 rgb outputs]
#define SM_B1S    16384    // 64 f32
#define SM_W2SIG  16640    // 64 f32
#define SM_B2RS   16896    // 32 f32
#define SM_B2SIG  17024    // 1 f32
#define SM_TAPS   17152    // 4 warps x 32 x 12 int2 = 12288
#define SM_FEATS  29440    // 4 warps x 2 rays x (32*33) f32 = 33792
#define SM_TOTAL  63360

// ---------- packed f32x2 helpers ----------
__device__ __forceinline__ u64 ffma2(u64 a, u64 b, u64 c) {
    u64 r; asm("fma.rn.f32x2 %0,%1,%2,%3;" : "=l"(r) : "l"(a), "l"(b), "l"(c)); return r;
}
__device__ __forceinline__ u64 pack2(float lo, float hi) {
    u64 r; asm("mov.b64 %0,{%1,%2};" : "=l"(r) : "f"(lo), "f"(hi)); return r;
}
__device__ __forceinline__ void unpack2(u64 d, float& lo, float& hi) {
    asm("mov.b64 {%0,%1},%2;" : "=f"(lo), "=f"(hi) : "l"(d));
}
__device__ __forceinline__ float softplus_f(float x) {
    return fmaxf(x, 0.f) + __logf(1.f + __expf(-fabsf(x)));
}

// ---------- kernel 0: [np][C][HW] -> [np][HW][C] tiled transpose ----------
__global__ void transpose_kernel(const float* __restrict__ in) {
    __shared__ float tile[32][33];
    int np  = blockIdx.y;
    int hw0 = blockIdx.x * 32;
    int tx = threadIdx.x, ty = threadIdx.y;
#pragma unroll
    for (int i = 0; i < 4; i++) {
        int cc = ty * 4 + i;
        tile[cc][tx] = in[(np * 32 + cc) * HW + hw0 + tx];
    }
    __syncthreads();
#pragma unroll
    for (int i = 0; i < 4; i++) {
        int row = ty * 4 + i;
        g_planesT[(size_t)(np * HW + hw0 + row) * 32 + tx] = tile[tx][row];
    }
}

// ---------- kernel 1: renderer, one warp per 2 rays ----------
__global__ __launch_bounds__(THREADS, 3) void render_kernel(
    const float* __restrict__ orig, const float* __restrict__ dirs,
    const float* __restrict__ w1, const float* __restrict__ b1,
    const float* __restrict__ w2, const float* __restrict__ b2,
    float* __restrict__ out)
{
    extern __shared__ __align__(16) unsigned char smem[];
    float* w1s    = (float*)(smem + SM_W1S);
    float* w2rs   = (float*)(smem + SM_W2RS);
    float* b1s    = (float*)(smem + SM_B1S);
    float* w2sigs = (float*)(smem + SM_W2SIG);
    float* b2rs   = (float*)(smem + SM_B2RS);
    float* b2sigp = (float*)(smem + SM_B2SIG);
    int2*  taps   = (int2*)(smem + SM_TAPS);
    float* featsb = (float*)(smem + SM_FEATS);

    const int tid = threadIdx.x;
    for (int i = tid; i < 2048; i += THREADS) w1s[i] = w1[i];
    if (tid < 64) b1s[tid] = b1[tid];
    for (int i = tid; i < 64 * 33; i += THREADS) {
        int j = i / 33, k = i - j * 33;
        float v = w2[i];
        if (k == 0) w2sigs[j] = v; else w2rs[j * 32 + (k - 1)] = v;
    }
    if (tid < 32) b2rs[tid] = b2[tid + 1];
    if (tid == 0) b2sigp[0] = b2[0];
    __syncthreads();

    const int w = tid >> 5, lane = tid & 31;
    const int rg0 = blockIdx.x * RPB + w * RPW;   // first ray of this warp
    const unsigned FULL = 0xffffffffu;

    const float t   = (lane + 0.5f) * 0.03125f;
    const float dep = 2.25f + 1.05f * t;

    // ---- stage 1+2 per ray: taps (lane = sample), then shuffle-free gather ----
#pragma unroll
    for (int r = 0; r < RPW; r++) {
        const int rg = rg0 + r;
        const int n  = rg >> 14;
        const float ox = orig[rg * 3 + 0], oy = orig[rg * 3 + 1], oz = orig[rg * 3 + 2];
        const float dx = dirs[rg * 3 + 0], dy = dirs[rg * 3 + 1], dz = dirs[rg * 3 + 2];
        const float cx = 2.f * fmaf(dep, dx, ox);
        const float cy = 2.f * fmaf(dep, dy, oy);
        const float cz = 2.f * fmaf(dep, dz, oz);

#pragma unroll
        for (int p = 0; p < 3; p++) {
            float u = (p == 0) ? cx : (p == 1) ? cy : cx;
            float v = (p == 0) ? cy : (p == 1) ? cz : cz;
            float ix = ((u + 1.f) * 0.5f) * 255.f;
            float iy = ((v + 1.f) * 0.5f) * 255.f;
            float fx0 = floorf(ix), fy0 = floorf(iy);
            float a0 = ix - fx0, a1 = (fx0 + 1.f) - ix;
            float bb0 = iy - fy0, bb1 = (fy0 + 1.f) - iy;
            int ix0 = (int)fminf(fmaxf(fx0, 0.f), 255.f);
            int ix1 = (int)fminf(fmaxf(fx0 + 1.f, 0.f), 255.f);
            int iy0 = (int)fminf(fmaxf(fy0, 0.f), 255.f);
            int iy1 = (int)fminf(fmaxf(fy0 + 1.f, 0.f), 255.f);
            int base = (n * 3 + p) * (HW * 32);
            int r0 = base + iy0 * (256 * 32);
            int r1 = base + iy1 * (256 * 32);
            int o = (w * 32 + lane) * 12 + p * 4;
            taps[o + 0] = make_int2(r0 + ix0 * 32, __float_as_int(a1 * bb1));
            taps[o + 1] = make_int2(r0 + ix1 * 32, __float_as_int(a0 * bb1));
            taps[o + 2] = make_int2(r1 + ix0 * 32, __float_as_int(a1 * bb0));
            taps[o + 3] = make_int2(r1 + ix1 * 32, __float_as_int(a0 * bb0));
        }
        __syncwarp();

        // gather: lanes = 8 channel-quads x 4 samples; each lane privately
        // accumulates all 12 taps of its sample for its 4 channels.
        {
            const int q    = lane & 7;           // channel quad
            const int sub  = lane >> 3;          // sample sub-index
            const int cpos = q * 4;
            float* feats = featsb + (w * 2 + r) * (32 * 33);
#pragma unroll 2
            for (int sb = 0; sb < 32; sb += 4) {
                const int s = sb + sub;
                float a0 = 0.f, a1 = 0.f, a2 = 0.f, a3 = 0.f;
#pragma unroll
                for (int tp = 0; tp < 12; tp++) {
                    int2 tw = taps[(w * 32 + s) * 12 + tp];
                    float wt = __int_as_float(tw.y);
                    const float4 v = *(const float4*)&g_planesT[tw.x + cpos];
                    a0 = fmaf(wt, v.x, a0);
                    a1 = fmaf(wt, v.y, a1);
                    a2 = fmaf(wt, v.z, a2);
                    a3 = fmaf(wt, v.w, a3);
                }
                float* f = feats + s * 33 + cpos;
                f[0] = a0 * (1.f / 3.f);
                f[1] = a1 * (1.f / 3.f);
                f[2] = a2 * (1.f / 3.f);
                f[3] = a3 * (1.f / 3.f);
            }
        }
        __syncwarp();
    }

    // ---- MLP for both samples (lane's sample of ray0 and ray1) ----
    const float* frow0 = featsb + (w * 2 + 0) * (32 * 33) + lane * 33;
    const float* frow1 = featsb + (w * 2 + 1) * (32 * 33) + lane * 33;

    const float b2sig = b2sigp[0];
    float sig0 = b2sig, sig1 = b2sig;
    u64 a20[16], a21[16];
    const u64* b2d = (const u64*)b2rs;
#pragma unroll
    for (int k = 0; k < 16; k++) { a20[k] = b2d[k]; a21[k] = b2d[k]; }

    const ulonglong2* w1d2 = (const ulonglong2*)w1s;
    const ulonglong2* w2d2 = (const ulonglong2*)w2rs;
    const u64* b1d = (const u64*)b1s;

#pragma unroll
    for (int q = 0; q < 4; q++) {       // 16 hidden units per quarter
        u64 ac0[8], ac1[8];
#pragma unroll
        for (int jp = 0; jp < 8; jp++) { ac0[jp] = b1d[q * 8 + jp]; ac1[jp] = ac0[jp]; }

#pragma unroll 4
        for (int cc = 0; cc < 32; cc++) {
            float f0 = frow0[cc], f1 = frow1[cc];
            u64 f02 = pack2(f0, f0), f12 = pack2(f1, f1);
            const ulonglong2* wr = w1d2 + cc * 16 + q * 4;
#pragma unroll
            for (int jq = 0; jq < 4; jq++) {
                ulonglong2 ww = wr[jq];
                ac0[2 * jq]     = ffma2(f02, ww.x, ac0[2 * jq]);
                ac0[2 * jq + 1] = ffma2(f02, ww.y, ac0[2 * jq + 1]);
                ac1[2 * jq]     = ffma2(f12, ww.x, ac1[2 * jq]);
                ac1[2 * jq + 1] = ffma2(f12, ww.y, ac1[2 * jq + 1]);
            }
        }
        // consume the 16 hidden units of this quarter into layer 2
#pragma unroll 4
        for (int jp = 0; jp < 8; jp++) {
            int j0 = q * 16 + 2 * jp;
            float l0, h0, l1, h1;
            unpack2(ac0[jp], l0, h0);
            unpack2(ac1[jp], l1, h1);
            float h00 = softplus_f(l0), h01 = softplus_f(h0);
            float h10 = softplus_f(l1), h11 = softplus_f(h1);
            float ws0 = w2sigs[j0], ws1 = w2sigs[j0 + 1];
            sig0 = fmaf(h00, ws0, sig0); sig0 = fmaf(h01, ws1, sig0);
            sig1 = fmaf(h10, ws0, sig1); sig1 = fmaf(h11, ws1, sig1);
            u64 p00 = pack2(h00, h00), p01 = pack2(h01, h01);
            u64 p10 = pack2(h10, h10), p11 = pack2(h11, h11);
            const ulonglong2* wr0 = w2d2 + j0 * 8;
#pragma unroll
            for (int kq = 0; kq < 8; kq++) {
                ulonglong2 ww0 = wr0[kq];
                ulonglong2 ww1 = wr0[8 + kq];
                u64 v0 = ffma2(p00, ww0.x, a20[2 * kq]);
                u64 v1 = ffma2(p00, ww0.y, a20[2 * kq + 1]);
                a20[2 * kq]     = ffma2(p01, ww1.x, v0);
                a20[2 * kq + 1] = ffma2(p01, ww1.y, v1);
                u64 u0 = ffma2(p10, ww0.x, a21[2 * kq]);
                u64 u1 = ffma2(p10, ww0.y, a21[2 * kq + 1]);
                a21[2 * kq]     = ffma2(p11, ww1.x, u0);
                a21[2 * kq + 1] = ffma2(p11, ww1.y, u1);
            }
        }
    }

    // ---- ray marching per ray: warp scan over samples (lane = s) ----
#pragma unroll
    for (int r = 0; r < RPW; r++) {
        float sig = (r == 0) ? sig0 : sig1;
        float rgb[32];
#pragma unroll
        for (int k = 0; k < 16; k++) {
            u64 av = (r == 0) ? a20[k] : a21[k];
            float lo, hi; unpack2(av, lo, hi);
            rgb[2 * k]     = __fdividef(1.002f, 1.f + __expf(-lo)) - 0.001f;
            rgb[2 * k + 1] = __fdividef(1.002f, 1.f + __expf(-hi)) - 0.001f;
        }

        float sig_n = __shfl_down_sync(FULL, sig, 1);
        float dep_n = __shfl_down_sync(FULL, dep, 1);
        float alpha;
        if (lane < 31) {
            float delta = dep_n - dep;
            float dm = 0.5f * (sig + sig_n);
            float dens = softplus_f(dm - 1.f);
            alpha = 1.f - __expf(-delta * dens);
        } else {
            alpha = 0.f;
        }
        float gg = 1.f - alpha + 1e-10f;
        float pscan = gg;
#pragma unroll
        for (int off = 1; off < 32; off <<= 1) {
            float v = __shfl_up_sync(FULL, pscan, off);
            if (lane >= off) pscan *= v;
        }
        float T = __shfl_up_sync(FULL, pscan, 1);
        if (lane == 0) T = 1.f;
        float wgt = alpha * T;
        float wprev = __shfl_up_sync(FULL, wgt, 1);
        if (lane == 0) wprev = 0.f;
        float coeff = 0.5f * (wgt + wprev);

#pragma unroll
        for (int k = 0; k < 32; k++) rgb[k] *= coeff;
#pragma unroll
        for (int off = 16; off >= 1; off >>= 1) {
#pragma unroll
            for (int k = 0; k < 32; k++) rgb[k] += __shfl_xor_sync(FULL, rgb[k], off);
        }
        if (lane == 0) {
            float4* o4 = (float4*)(out + (rg0 + r) * 32);
#pragma unroll
            for (int k = 0; k < 8; k++)
                o4[k] = make_float4(rgb[4 * k], rgb[4 * k + 1], rgb[4 * k + 2], rgb[4 * k + 3]);
        }
    }
}

extern "C" void kernel_launch(void* const* d_in, const int* in_sizes, int n_in,
                              void* d_out, int out_size) {
    const float* vol  = (const float*)d_in[0];  // [2,3,32,256,256]
    const float* orig = (const float*)d_in[1];  // [2,16384,3]
    const float* dirs = (const float*)d_in[2];  // [2,16384,3]
    const float* w1   = (const float*)d_in[3];  // [32,64]
    const float* b1   = (const float*)d_in[4];  // [64]
    const float* w2   = (const float*)d_in[5];  // [64,33]
    const float* b2   = (const float*)d_in[6];  // [33]
    float* out = (float*)d_out;

    static int inited = 0;
    if (!inited) {
        cudaFuncSetAttribute(render_kernel,
                             cudaFuncAttributeMaxDynamicSharedMemorySize, SM_TOTAL);
        inited = 1;
    }

    dim3 tb(32, 8);
    dim3 tg(HW / 32, N_BATCH * 3);
    transpose_kernel<<<tg, tb>>>(vol);

    render_kernel<<<NRAYS / RPB, THREADS, SM_TOTAL>>>(orig, dirs, w1, b1, w2, b2, out);
}

// round 10
// speedup vs baseline: 2.0014x; 1.0462x over previous
#include <cuda_runtime.h>
#include <cuda_fp16.h>

// Problem constants (fixed by the dataset)
#define N_BATCH 2
#define HW 65536          // 256*256
#define NRAYS 32768       // N_BATCH * 16384
#define RPW 2             // rays per warp
#define RPB 8             // rays per block (4 warps x 2)
#define THREADS 128

typedef unsigned long long u64;

// channels-last fp16 copy of the planes: [(n*3+p)][hw][c]
__device__ __half g_planesH[(size_t)N_BATCH * 3 * HW * 32];

// ---- dynamic smem layout (bytes) ----
#define SM_W1S    0        // 2048 f32  [c][j]
#define SM_W2RS   8192     // 2048 f32  [j][32 rgb outputs]
#define SM_B1S    16384    // 64 f32
#define SM_W2SIG  16640    // 64 f32
#define SM_B2RS   16896    // 32 f32
#define SM_B2SIG  17024    // 1 f32
#define SM_TAPS   17152    // 4 warps x 32 x 12 int2 = 12288
#define SM_FEATS  29440    // 4 warps x 2 rays x (32*33) f32 = 33792
#define SM_TOTAL  63360

// ---------- packed f32x2 helpers ----------
__device__ __forceinline__ u64 ffma2(u64 a, u64 b, u64 c) {
    u64 r; asm("fma.rn.f32x2 %0,%1,%2,%3;" : "=l"(r) : "l"(a), "l"(b), "l"(c)); return r;
}
__device__ __forceinline__ u64 pack2(float lo, float hi) {
    u64 r; asm("mov.b64 %0,{%1,%2};" : "=l"(r) : "f"(lo), "f"(hi)); return r;
}
__device__ __forceinline__ void unpack2(u64 d, float& lo, float& hi) {
    asm("mov.b64 {%0,%1},%2;" : "=f"(lo), "=f"(hi) : "l"(d));
}
__device__ __forceinline__ float softplus_f(float x) {
    return fmaxf(x, 0.f) + __logf(1.f + __expf(-fabsf(x)));
}

// ---------- kernel 0: [np][C][HW] f32 -> [np][HW][C] fp16 transpose ----------
__global__ void transpose_kernel(const float* __restrict__ in) {
    __shared__ float tile[32][33];
    int np  = blockIdx.y;
    int hw0 = blockIdx.x * 32;
    int tx = threadIdx.x, ty = threadIdx.y;
#pragma unroll
    for (int i = 0; i < 4; i++) {
        int cc = ty * 4 + i;
        tile[cc][tx] = in[(np * 32 + cc) * HW + hw0 + tx];
    }
    __syncthreads();
#pragma unroll
    for (int i = 0; i < 4; i++) {
        int row = ty * 4 + i;
        g_planesH[(size_t)(np * HW + hw0 + row) * 32 + tx] = __float2half(tile[tx][row]);
    }
}

// ---------- kernel 1: renderer, one warp per 2 rays ----------
__global__ __launch_bounds__(THREADS, 3) void render_kernel(
    const float* __restrict__ orig, const float* __restrict__ dirs,
    const float* __restrict__ w1, const float* __restrict__ b1,
    const float* __restrict__ w2, const float* __restrict__ b2,
    float* __restrict__ out)
{
    extern __shared__ __align__(16) unsigned char smem[];
    float* w1s    = (float*)(smem + SM_W1S);
    float* w2rs   = (float*)(smem + SM_W2RS);
    float* b1s    = (float*)(smem + SM_B1S);
    float* w2sigs = (float*)(smem + SM_W2SIG);
    float* b2rs   = (float*)(smem + SM_B2RS);
    float* b2sigp = (float*)(smem + SM_B2SIG);
    int2*  taps   = (int2*)(smem + SM_TAPS);
    float* featsb = (float*)(smem + SM_FEATS);

    const int tid = threadIdx.x;
    for (int i = tid; i < 2048; i += THREADS) w1s[i] = w1[i];
    if (tid < 64) b1s[tid] = b1[tid];
    for (int i = tid; i < 64 * 33; i += THREADS) {
        int j = i / 33, k = i - j * 33;
        float v = w2[i];
        if (k == 0) w2sigs[j] = v; else w2rs[j * 32 + (k - 1)] = v;
    }
    if (tid < 32) b2rs[tid] = b2[tid + 1];
    if (tid == 0) b2sigp[0] = b2[0];
    __syncthreads();

    const int w = tid >> 5, lane = tid & 31;
    const int rg0 = blockIdx.x * RPB + w * RPW;   // first ray of this warp
    const unsigned FULL = 0xffffffffu;

    const float t   = (lane + 0.5f) * 0.03125f;
    const float dep = 2.25f + 1.05f * t;

    // ---- stage 1+2 per ray: taps (lane = sample), then shuffle-free gather ----
#pragma unroll
    for (int r = 0; r < RPW; r++) {
        const int rg = rg0 + r;
        const int n  = rg >> 14;
        const float ox = orig[rg * 3 + 0], oy = orig[rg * 3 + 1], oz = orig[rg * 3 + 2];
        const float dx = dirs[rg * 3 + 0], dy = dirs[rg * 3 + 1], dz = dirs[rg * 3 + 2];
        const float cx = 2.f * fmaf(dep, dx, ox);
        const float cy = 2.f * fmaf(dep, dy, oy);
        const float cz = 2.f * fmaf(dep, dz, oz);

#pragma unroll
        for (int p = 0; p < 3; p++) {
            float u = (p == 0) ? cx : (p == 1) ? cy : cx;
            float v = (p == 0) ? cy : (p == 1) ? cz : cz;
            float ix = ((u + 1.f) * 0.5f) * 255.f;
            float iy = ((v + 1.f) * 0.5f) * 255.f;
            float fx0 = floorf(ix), fy0 = floorf(iy);
            float a0 = ix - fx0, a1 = (fx0 + 1.f) - ix;
            float bb0 = iy - fy0, bb1 = (fy0 + 1.f) - iy;
            int ix0 = (int)fminf(fmaxf(fx0, 0.f), 255.f);
            int ix1 = (int)fminf(fmaxf(fx0 + 1.f, 0.f), 255.f);
            int iy0 = (int)fminf(fmaxf(fy0, 0.f), 255.f);
            int iy1 = (int)fminf(fmaxf(fy0 + 1.f, 0.f), 255.f);
            int base = (n * 3 + p) * (HW * 32);
            int r0 = base + iy0 * (256 * 32);
            int r1 = base + iy1 * (256 * 32);
            int o = (w * 32 + lane) * 12 + p * 4;
            taps[o + 0] = make_int2(r0 + ix0 * 32, __float_as_int(a1 * bb1));
            taps[o + 1] = make_int2(r0 + ix1 * 32, __float_as_int(a0 * bb1));
            taps[o + 2] = make_int2(r1 + ix0 * 32, __float_as_int(a1 * bb0));
            taps[o + 3] = make_int2(r1 + ix1 * 32, __float_as_int(a0 * bb0));
        }
        __syncwarp();

        // gather: lanes = 8 channel-quads x 4 samples; each lane privately
        // accumulates all 12 taps of its sample for its 4 channels (fp16 loads).
        {
            const int q    = lane & 7;           // channel quad
            const int sub  = lane >> 3;          // sample sub-index
            const int cpos = q * 4;
            float* feats = featsb + (w * 2 + r) * (32 * 33);
#pragma unroll 2
            for (int sb = 0; sb < 32; sb += 4) {
                const int s = sb + sub;
                float a0 = 0.f, a1 = 0.f, a2 = 0.f, a3 = 0.f;
#pragma unroll
                for (int tp = 0; tp < 12; tp++) {
                    int2 tw = taps[(w * 32 + s) * 12 + tp];
                    float wt = __int_as_float(tw.y);
                    uint2 raw = *(const uint2*)&g_planesH[tw.x + cpos];
                    float2 f01 = __half22float2(*reinterpret_cast<__half2*>(&raw.x));
                    float2 f23 = __half22float2(*reinterpret_cast<__half2*>(&raw.y));
                    a0 = fmaf(wt, f01.x, a0);
                    a1 = fmaf(wt, f01.y, a1);
                    a2 = fmaf(wt, f23.x, a2);
                    a3 = fmaf(wt, f23.y, a3);
                }
                float* f = feats + s * 33 + cpos;
                f[0] = a0 * (1.f / 3.f);
                f[1] = a1 * (1.f / 3.f);
                f[2] = a2 * (1.f / 3.f);
                f[3] = a3 * (1.f / 3.f);
            }
        }
        __syncwarp();
    }

    // ---- MLP for both samples (lane's sample of ray0 and ray1) ----
    const float* frow0 = featsb + (w * 2 + 0) * (32 * 33) + lane * 33;
    const float* frow1 = featsb + (w * 2 + 1) * (32 * 33) + lane * 33;

    const float b2sig = b2sigp[0];
    float sig0 = b2sig, sig1 = b2sig;
    u64 a20[16], a21[16];
    const u64* b2d = (const u64*)b2rs;
#pragma unroll
    for (int k = 0; k < 16; k++) { a20[k] = b2d[k]; a21[k] = b2d[k]; }

    const ulonglong2* w1d2 = (const ulonglong2*)w1s;
    const ulonglong2* w2d2 = (const ulonglong2*)w2rs;
    const u64* b1d = (const u64*)b1s;

#pragma unroll
    for (int q = 0; q < 4; q++) {       // 16 hidden units per quarter
        u64 ac0[8], ac1[8];
#pragma unroll
        for (int jp = 0; jp < 8; jp++) { ac0[jp] = b1d[q * 8 + jp]; ac1[jp] = ac0[jp]; }

#pragma unroll 4
        for (int cc = 0; cc < 32; cc++) {
            float f0 = frow0[cc], f1 = frow1[cc];
            u64 f02 = pack2(f0, f0), f12 = pack2(f1, f1);
            const ulonglong2* wr = w1d2 + cc * 16 + q * 4;
#pragma unroll
            for (int jq = 0; jq < 4; jq++) {
                ulonglong2 ww = wr[jq];
                ac0[2 * jq]     = ffma2(f02, ww.x, ac0[2 * jq]);
                ac0[2 * jq + 1] = ffma2(f02, ww.y, ac0[2 * jq + 1]);
                ac1[2 * jq]     = ffma2(f12, ww.x, ac1[2 * jq]);
                ac1[2 * jq + 1] = ffma2(f12, ww.y, ac1[2 * jq + 1]);
            }
        }
        // consume the 16 hidden units of this quarter into layer 2
#pragma unroll 4
        for (int jp = 0; jp < 8; jp++) {
            int j0 = q * 16 + 2 * jp;
            float l0, h0, l1, h1;
            unpack2(ac0[jp], l0, h0);
            unpack2(ac1[jp], l1, h1);
            float h00 = softplus_f(l0), h01 = softplus_f(h0);
            float h10 = softplus_f(l1), h11 = softplus_f(h1);
            float ws0 = w2sigs[j0], ws1 = w2sigs[j0 + 1];
            sig0 = fmaf(h00, ws0, sig0); sig0 = fmaf(h01, ws1, sig0);
            sig1 = fmaf(h10, ws0, sig1); sig1 = fmaf(h11, ws1, sig1);
            u64 p00 = pack2(h00, h00), p01 = pack2(h01, h01);
            u64 p10 = pack2(h10, h10), p11 = pack2(h11, h11);
            const ulonglong2* wr0 = w2d2 + j0 * 8;
#pragma unroll
            for (int kq = 0; kq < 8; kq++) {
                ulonglong2 ww0 = wr0[kq];
                ulonglong2 ww1 = wr0[8 + kq];
                u64 v0 = ffma2(p00, ww0.x, a20[2 * kq]);
                u64 v1 = ffma2(p00, ww0.y, a20[2 * kq + 1]);
                a20[2 * kq]     = ffma2(p01, ww1.x, v0);
                a20[2 * kq + 1] = ffma2(p01, ww1.y, v1);
                u64 u0 = ffma2(p10, ww0.x, a21[2 * kq]);
                u64 u1 = ffma2(p10, ww0.y, a21[2 * kq + 1]);
                a21[2 * kq]     = ffma2(p11, ww1.x, u0);
                a21[2 * kq + 1] = ffma2(p11, ww1.y, u1);
            }
        }
    }

    // ---- ray marching per ray: warp scan over samples (lane = s) ----
#pragma unroll
    for (int r = 0; r < RPW; r++) {
        float sig = (r == 0) ? sig0 : sig1;
        float rgb[32];
#pragma unroll
        for (int k = 0; k < 16; k++) {
            u64 av = (r == 0) ? a20[k] : a21[k];
            float lo, hi; unpack2(av, lo, hi);
            rgb[2 * k]     = __fdividef(1.002f, 1.f + __expf(-lo)) - 0.001f;
            rgb[2 * k + 1] = __fdividef(1.002f, 1.f + __expf(-hi)) - 0.001f;
        }

        float sig_n = __shfl_down_sync(FULL, sig, 1);
        float dep_n = __shfl_down_sync(FULL, dep, 1);
        float alpha;
        if (lane < 31) {
            float delta = dep_n - dep;
            float dm = 0.5f * (sig + sig_n);
            float dens = softplus_f(dm - 1.f);
            alpha = 1.f - __expf(-delta * dens);
        } else {
            alpha = 0.f;
        }
        float gg = 1.f - alpha + 1e-10f;
        float pscan = gg;
#pragma unroll
        for (int off = 1; off < 32; off <<= 1) {
            float v = __shfl_up_sync(FULL, pscan, off);
            if (lane >= off) pscan *= v;
        }
        float T = __shfl_up_sync(FULL, pscan, 1);
        if (lane == 0) T = 1.f;
        float wgt = alpha * T;
        float wprev = __shfl_up_sync(FULL, wgt, 1);
        if (lane == 0) wprev = 0.f;
        float coeff = 0.5f * (wgt + wprev);

#pragma unroll
        for (int k = 0; k < 32; k++) rgb[k] *= coeff;
#pragma unroll
        for (int off = 16; off >= 1; off >>= 1) {
#pragma unroll
            for (int k = 0; k < 32; k++) rgb[k] += __shfl_xor_sync(FULL, rgb[k], off);
        }
        if (lane == 0) {
            float4* o4 = (float4*)(out + (rg0 + r) * 32);
#pragma unroll
            for (int k = 0; k < 8; k++)
                o4[k] = make_float4(rgb[4 * k], rgb[4 * k + 1], rgb[4 * k + 2], rgb[4 * k + 3]);
        }
    }
}

extern "C" void kernel_launch(void* const* d_in, const int* in_sizes, int n_in,
                              void* d_out, int out_size) {
    const float* vol  = (const float*)d_in[0];  // [2,3,32,256,256]
    const float* orig = (const float*)d_in[1];  // [2,16384,3]
    const float* dirs = (const float*)d_in[2];  // [2,16384,3]
    const float* w1   = (const float*)d_in[3];  // [32,64]
    const float* b1   = (const float*)d_in[4];  // [64]
    const float* w2   = (const float*)d_in[5];  // [64,33]
    const float* b2   = (const float*)d_in[6];  // [33]
    float* out = (float*)d_out;

    static int inited = 0;
    if (!inited) {
        cudaFuncSetAttribute(render_kernel,
                             cudaFuncAttributeMaxDynamicSharedMemorySize, SM_TOTAL);
        inited = 1;
    }

    dim3 tb(32, 8);
    dim3 tg(HW / 32, N_BATCH * 3);
    transpose_kernel<<<tg, tb>>>(vol);

    render_kernel<<<NRAYS / RPB, THREADS, SM_TOTAL>>>(orig, dirs, w1, b1, w2, b2, out);
}